// round 5
// baseline (speedup 1.0000x reference)
#include <cuda_runtime.h>
#include <cstdint>

#define BB 2
#define NPTS 8192
#define BLK 128             // threads per dist block
#define Q 8                 // resident ref rows per thread
#define RP (Q/2)            // rowpairs
#define TILEM (BLK*Q)       // 1024 refs per block
#define MT (NPTS/TILEM)     // 8 ref tiles
#define SPLITC 256          // pred candidates per block
#define NS (NPTS/SPLITC)    // 32 splits
#define NGROUP (SPLITC/4)   // 64 groups of 4 candidates
#define FBLKS 128
#define FBLK_T 128

typedef unsigned long long ull;

// Scratch (device globals; no allocations allowed)
__device__ float4   g_p4[BB*NPTS];     // pred: (-2x, -2y, -2z, |p|^2)
__device__ ull      g_closest[BB*NPTS];// per ref m: (fkey(val)<<32)|pred_idx
__device__ unsigned g_minxy[BB*NPTS];  // per pred n: bits of clamped min d2
__device__ double   g_part[FBLKS*4];
__device__ unsigned g_ctr;

__device__ __forceinline__ ull fma2(ull a, ull b, ull c){
    ull d; asm("fma.rn.f32x2 %0, %1, %2, %3;" : "=l"(d) : "l"(a), "l"(b), "l"(c)); return d;
}
__device__ __forceinline__ ull add2(ull a, ull b){
    ull d; asm("add.rn.f32x2 %0, %1, %2;" : "=l"(d) : "l"(a), "l"(b)); return d;
}
__device__ __forceinline__ ull pk2(float x){
    ull v; asm("mov.b64 %0, {%1, %2};" : "=l"(v)
               : "r"(__float_as_uint(x)), "r"(__float_as_uint(x)));
    return v;
}
__device__ __forceinline__ ull pk2d(float lo, float hi){
    ull v; asm("mov.b64 %0, {%1, %2};" : "=l"(v)
               : "r"(__float_as_uint(lo)), "r"(__float_as_uint(hi)));
    return v;
}
__device__ __forceinline__ void unpk(ull v, float& lo, float& hi){
    unsigned a, b;
    asm("mov.b64 {%0, %1}, %2;" : "=r"(a), "=r"(b) : "l"(v));
    lo = __uint_as_float(a); hi = __uint_as_float(b);
}
__device__ __forceinline__ unsigned fkey(float f){
    unsigned b = __float_as_uint(f);
    return b ^ ((unsigned)((int)b >> 31) | 0x80000000u);
}
__device__ __forceinline__ float funkey(unsigned u){
    unsigned b = u ^ ((u & 0x80000000u) ? 0x80000000u : 0xFFFFFFFFu);
    return __uint_as_float(b);
}

__global__ void prep_kernel(const float* __restrict__ pred_pts) {
    int i = blockIdx.x * blockDim.x + threadIdx.x;
    if (i == 0) g_ctr = 0;
    if (i >= BB * NPTS) return;
    float x = pred_pts[3*i], y = pred_pts[3*i+1], z = pred_pts[3*i+2];
    g_p4[i] = make_float4(-2.f*x, -2.f*y, -2.f*z, x*x + y*y + z*z);
    g_closest[i] = 0xFFFFFFFFFFFFFFFFull;
    g_minxy[i]   = 0x7F800000u;   // +inf bits
}

// Fused: each (ref m, pred n) pair evaluated ONCE.
//   val = -2 p.r + |p|^2  (row-argmin key for ref m; d2 = val + |r|^2)
//   rows (ref, argmin over pred) resident in regs; cols (pred, min over ref) via
//   per-candidate 2-shuffle + 8-lane red.global.min.
__global__ void dist_kernel(const float* __restrict__ ref_pts) {
    __shared__ __align__(16) ull scand[SPLITC*4];  // per cand: cx2, cy2, cz2, cc2 (dup-packed)
    const int b     = blockIdx.z;
    const int tile  = blockIdx.x;
    const int split = blockIdx.y;
    const int tid   = threadIdx.x;
    const int lane  = tid & 31;
    const int base_m = b*NPTS + tile*TILEM;
    const int base_c = b*NPTS + split*SPLITC;
    const int cidx0  = split*SPLITC;               // pred index base within batch

    // Stage candidates (duplicate-pack for f32x2 broadcast)
    for (int c = tid; c < SPLITC; c += BLK) {
        float4 v = g_p4[base_c + c];
        ull* d = scand + c*4;
        d[0] = pk2(v.x); d[1] = pk2(v.y); d[2] = pk2(v.z); d[3] = pk2(v.w);
    }

    // Resident ref rows: rowpair k holds m_lo = tid + 2k*BLK, m_hi = tid + (2k+1)*BLK
    ull rx2[RP], ry2[RP], rz2[RP], rm2p[RP];
    #pragma unroll
    for (int k = 0; k < RP; k++) {
        const int m0 = base_m + tid + (2*k)*BLK;
        const int m1 = m0 + BLK;
        const float ax = ref_pts[3*m0], ay = ref_pts[3*m0+1], az = ref_pts[3*m0+2];
        const float bx = ref_pts[3*m1], by = ref_pts[3*m1+1], bz = ref_pts[3*m1+2];
        rx2[k] = pk2d(ax, bx); ry2[k] = pk2d(ay, by); rz2[k] = pk2d(az, bz);
        rm2p[k] = pk2d(ax*ax + ay*ay + az*az, bx*bx + by*by + bz*bz);
    }
    const float INFF = __int_as_float(0x7F800000);
    float rvL[RP], rvH[RP];
    int   riL[RP], riH[RP];
    #pragma unroll
    for (int k = 0; k < RP; k++) { rvL[k] = INFF; rvH[k] = INFF; riL[k] = 0; riH[k] = 0; }

    __syncthreads();

    for (int g = 0; g < NGROUP; g++) {
        const ulonglong2* cp = (const ulonglong2*)(scand + (g << 4));
        ulonglong2 ca[4], cb[4];          // ca = {cx2, cy2}, cb = {cz2, cc2}
        #pragma unroll
        for (int c = 0; c < 4; c++) { ca[c] = cp[2*c]; cb[c] = cp[2*c + 1]; }

        float colacc[4] = {INFF, INFF, INFF, INFF};
        const int cb0 = cidx0 + (g << 2);

        #pragma unroll
        for (int k = 0; k < RP; k++) {
            float vlo[4], vhi[4];
            #pragma unroll
            for (int c = 0; c < 4; c++) {
                ull v2 = fma2(ca[c].x, rx2[k], fma2(ca[c].y, ry2[k], fma2(cb[c].x, rz2[k], cb[c].y)));
                ull d2 = add2(v2, rm2p[k]);
                float dlo, dhi; unpk(d2, dlo, dhi);
                colacc[c] = fminf(colacc[c], fminf(dlo, dhi));
                unpk(v2, vlo[c], vhi[c]);
            }
            const float glo = fminf(fminf(vlo[0], vlo[1]), fminf(vlo[2], vlo[3]));
            const float ghi = fminf(fminf(vhi[0], vhi[1]), fminf(vhi[2], vhi[3]));
            if (glo < rvL[k]) {   // rare
                if (vlo[0] < rvL[k]) { rvL[k] = vlo[0]; riL[k] = cb0;     }
                if (vlo[1] < rvL[k]) { rvL[k] = vlo[1]; riL[k] = cb0 + 1; }
                if (vlo[2] < rvL[k]) { rvL[k] = vlo[2]; riL[k] = cb0 + 2; }
                if (vlo[3] < rvL[k]) { rvL[k] = vlo[3]; riL[k] = cb0 + 3; }
            }
            if (ghi < rvH[k]) {   // rare
                if (vhi[0] < rvH[k]) { rvH[k] = vhi[0]; riH[k] = cb0;     }
                if (vhi[1] < rvH[k]) { rvH[k] = vhi[1]; riH[k] = cb0 + 1; }
                if (vhi[2] < rvH[k]) { rvH[k] = vhi[2]; riH[k] = cb0 + 2; }
                if (vhi[3] < rvH[k]) { rvH[k] = vhi[3]; riH[k] = cb0 + 3; }
            }
        }

        // Column merge: warp-partial (512 rows) -> global
        #pragma unroll
        for (int c = 0; c < 4; c++) {
            float v = colacc[c];
            v = fminf(v, __shfl_down_sync(0xFFFFFFFFu, v, 16));
            v = fminf(v, __shfl_down_sync(0xFFFFFFFFu, v, 8));
            if (lane < 8)
                atomicMin(&g_minxy[base_c + (g << 2) + c], __float_as_uint(fmaxf(v, 0.f)));
        }
    }

    // Flush resident rows (argmin partials over this block's 256 candidates)
    #pragma unroll
    for (int k = 0; k < RP; k++) {
        const int m0 = base_m + tid + (2*k)*BLK;
        atomicMin(&g_closest[m0],       ((ull)fkey(rvL[k]) << 32) | (unsigned)riL[k]);
        atomicMin(&g_closest[m0 + BLK], ((ull)fkey(rvH[k]) << 32) | (unsigned)riH[k]);
    }
}

// Finalization: per-element losses, warp-shuffle reduce, last-block combines
// (deterministic fixed-order trees; ticket only selects WHO combines).
__global__ void __launch_bounds__(FBLK_T) final_kernel(const float* __restrict__ pred_sdfs,
                                                       const float* __restrict__ pred_cols,
                                                       const float* __restrict__ ref_sdfs,
                                                       const float* __restrict__ ref_cols,
                                                       const float* __restrict__ ref_pts,
                                                       float* __restrict__ out) {
    const int i = blockIdx.x * FBLK_T + threadIdx.x;   // [0, BB*NPTS)
    const int b = i >> 13;
    const int lane = threadIdx.x & 31;
    const int wid = threadIdx.x >> 5;

    const ull p = g_closest[i];
    const unsigned idx = (unsigned)(p & 0xFFFFFFFFu);
    const float rx = ref_pts[3*i], ry = ref_pts[3*i+1], rz = ref_pts[3*i+2];
    const float rm2 = rx*rx + ry*ry + rz*rz;
    const float d_yx = fmaxf(funkey((unsigned)(p >> 32)) + rm2, 0.f);
    const float d_xy = __uint_as_float(g_minxy[i]);

    const float* pc = pred_cols + (size_t)i * 3;
    const float* rc = ref_cols + ((size_t)(b << 13) + idx) * 3;
    double vals[4];
    vals[0] = fabsf(ref_sdfs[(b << 13) + idx] - pred_sdfs[i]);
    vals[1] = (double)(fabsf(rc[0]-pc[0]) + fabsf(rc[1]-pc[1]) + fabsf(rc[2]-pc[2]));
    vals[2] = d_yx;
    vals[3] = d_xy;

    __shared__ double sred[4][4];   // [warp][k]
    #pragma unroll
    for (int k = 0; k < 4; k++) {
        double v = vals[k];
        #pragma unroll
        for (int s = 16; s > 0; s >>= 1) v += __shfl_down_sync(0xFFFFFFFFu, v, s);
        if (lane == 0) sred[wid][k] = v;
    }
    __syncthreads();
    if (threadIdx.x == 0) {
        #pragma unroll
        for (int k = 0; k < 4; k++)
            g_part[blockIdx.x * 4 + k] = sred[0][k] + sred[1][k] + sred[2][k] + sred[3][k];
    }

    __threadfence();
    __shared__ unsigned ticket;
    if (threadIdx.x == 0) ticket = atomicAdd(&g_ctr, 1u);
    __syncthreads();
    if (ticket != FBLKS - 1) return;

    __threadfence();
    volatile double* vp = (volatile double*)g_part;
    double tv[4];
    #pragma unroll
    for (int k = 0; k < 4; k++) tv[k] = vp[threadIdx.x * 4 + k];  // thread t = block t's partial
    #pragma unroll
    for (int k = 0; k < 4; k++) {
        double v = tv[k];
        #pragma unroll
        for (int s = 16; s > 0; s >>= 1) v += __shfl_down_sync(0xFFFFFFFFu, v, s);
        if (lane == 0) sred[wid][k] = v;
    }
    __syncthreads();
    if (threadIdx.x == 0) {
        double t0 = sred[0][0] + sred[1][0] + sred[2][0] + sred[3][0];
        double t1 = sred[0][1] + sred[1][1] + sred[2][1] + sred[3][1];
        double t2 = sred[0][2] + sred[1][2] + sred[2][2] + sred[3][2];
        double t3 = sred[0][3] + sred[1][3] + sred[2][3] + sred[3][3];
        out[0] = (float)(t0 / (double)(BB * NPTS));
        out[1] = (float)(t1 / (double)(BB * NPTS * 3));
        out[2] = (float)(t3 / (double)(BB * NPTS) + t2 / (double)(BB * NPTS));
    }
}

extern "C" void kernel_launch(void* const* d_in, const int* in_sizes, int n_in,
                              void* d_out, int out_size) {
    const float* pred_pts  = (const float*)d_in[0];
    const float* pred_sdfs = (const float*)d_in[1];
    const float* pred_cols = (const float*)d_in[2];
    const float* ref_pts   = (const float*)d_in[3];
    const float* ref_sdfs  = (const float*)d_in[4];
    const float* ref_cols  = (const float*)d_in[5];
    float* out = (float*)d_out;

    prep_kernel<<<(BB*NPTS + 255) / 256, 256>>>(pred_pts);
    dist_kernel<<<dim3(MT, NS, BB), BLK>>>(ref_pts);
    final_kernel<<<FBLKS, FBLK_T>>>(pred_sdfs, pred_cols, ref_sdfs, ref_cols, ref_pts, out);
}

// round 7
// speedup vs baseline: 1.0485x; 1.0485x over previous
#include <cuda_runtime.h>
#include <cstdint>

#define BB 2
#define NPTS 8192
#define BLK 256
#define QPT 4
#define NSPLIT 16
#define CHUNK (NPTS / NSPLIT)     // 512 candidates per block
#define GX (NPTS / (BLK * QPT))   // 8
#define FBLKS 128
#define FBLK_T 128

typedef unsigned long long ull;

// Scratch (device globals; no allocations allowed)
__device__ float g_px[BB*NPTS], g_py[BB*NPTS], g_pz[BB*NPTS], g_pc[BB*NPTS]; // pred: -2x,-2y,-2z,|p|^2
__device__ float g_rx[BB*NPTS], g_ry[BB*NPTS], g_rz[BB*NPTS], g_rc[BB*NPTS]; // ref:  -2x,-2y,-2z,|r|^2
__device__ ull      g_closest[BB*NPTS];   // packed (fkey(val)<<32)|pred_idx per ref point
__device__ unsigned g_minxy[BB*NPTS];     // fkey(min val) per pred point
__device__ double   g_part[FBLKS*4];
__device__ unsigned g_ctr;

__device__ __forceinline__ ull fma2(ull a, ull b, ull c){
    ull d; asm("fma.rn.f32x2 %0, %1, %2, %3;" : "=l"(d) : "l"(a), "l"(b), "l"(c)); return d;
}
__device__ __forceinline__ ull pk2(float x){
    ull v; asm("mov.b64 %0, {%1, %2};" : "=l"(v)
               : "r"(__float_as_uint(x)), "r"(__float_as_uint(x)));
    return v;
}
__device__ __forceinline__ void unpk(ull v, float& lo, float& hi){
    unsigned a, b;
    asm("mov.b64 {%0, %1}, %2;" : "=r"(a), "=r"(b) : "l"(v));
    lo = __uint_as_float(a); hi = __uint_as_float(b);
}
// Monotone float->uint key (handles negatives), invertible.
__device__ __forceinline__ unsigned fkey(float f){
    unsigned b = __float_as_uint(f);
    return b ^ ((unsigned)((int)b >> 31) | 0x80000000u);
}
__device__ __forceinline__ float funkey(unsigned u){
    unsigned b = u ^ ((u & 0x80000000u) ? 0x80000000u : 0xFFFFFFFFu);
    return __uint_as_float(b);
}

__global__ void prep_kernel(const float* __restrict__ pred_pts,
                            const float* __restrict__ ref_pts) {
    int i = blockIdx.x * blockDim.x + threadIdx.x;
    if (i == 0) g_ctr = 0;
    if (i >= BB * NPTS) return;
    float x = pred_pts[3*i], y = pred_pts[3*i+1], z = pred_pts[3*i+2];
    g_px[i] = -2.f*x; g_py[i] = -2.f*y; g_pz[i] = -2.f*z;
    g_pc[i] = x*x + y*y + z*z;
    x = ref_pts[3*i]; y = ref_pts[3*i+1]; z = ref_pts[3*i+2];
    g_rx[i] = -2.f*x; g_ry[i] = -2.f*y; g_rz[i] = -2.f*z;
    g_rc[i] = x*x + y*y + z*z;
    g_closest[i] = 0xFFFFFFFFFFFFFFFFull;
    g_minxy[i]   = 0xFFFFFFFFu;
}

// Fused distance kernel. blockIdx.y < NSPLIT: xy role (queries=pred, candidates=ref, plain min).
// blockIdx.y >= NSPLIT: yx role (queries=ref, candidates=pred, argmin).
// Score val = -2 q.c + |c|^2 = d2 - |q|^2 (same ordering as d2 for fixed query).
__global__ void __launch_bounds__(BLK) dist_kernel(const float* __restrict__ pred_pts,
                                                   const float* __restrict__ ref_pts) {
    __shared__ __align__(16) float sx[CHUNK], sy[CHUNK], sz[CHUNK], sc[CHUNK];
    const int b   = blockIdx.z;
    const bool yx = (blockIdx.y >= NSPLIT);
    const int cy  = yx ? (blockIdx.y - NSPLIT) : blockIdx.y;
    const int c0  = cy * CHUNK;
    const int q0  = blockIdx.x * (BLK * QPT) + threadIdx.x;
    const int base = b * NPTS + c0;

    const float* cx = yx ? g_px : g_rx;
    const float* cyy = yx ? g_py : g_ry;
    const float* cz = yx ? g_pz : g_rz;
    const float* cc = yx ? g_pc : g_rc;
    ((float2*)sx)[threadIdx.x] = ((const float2*)(cx  + base))[threadIdx.x];
    ((float2*)sy)[threadIdx.x] = ((const float2*)(cyy + base))[threadIdx.x];
    ((float2*)sz)[threadIdx.x] = ((const float2*)(cz  + base))[threadIdx.x];
    ((float2*)sc)[threadIdx.x] = ((const float2*)(cc  + base))[threadIdx.x];

    const float* qsrc = yx ? ref_pts : pred_pts;
    ull qx[QPT], qy[QPT], qz[QPT];
    #pragma unroll
    for (int q = 0; q < QPT; q++) {
        const float* qp = qsrc + (size_t)(b*NPTS + q0 + q*BLK) * 3;
        qx[q] = pk2(qp[0]); qy[q] = pk2(qp[1]); qz[q] = pk2(qp[2]);
    }
    __syncthreads();

    const ulonglong2* x2p = (const ulonglong2*)sx;
    const ulonglong2* y2p = (const ulonglong2*)sy;
    const ulonglong2* z2p = (const ulonglong2*)sz;
    const ulonglong2* c2p = (const ulonglong2*)sc;

    const float INFF = __int_as_float(0x7F800000);

    if (!yx) {
        float accL[QPT], accH[QPT];
        #pragma unroll
        for (int q = 0; q < QPT; q++) { accL[q] = INFF; accH[q] = INFF; }
        #pragma unroll 4
        for (int t = 0; t < CHUNK/4; t++) {
            const ulonglong2 xv = x2p[t], yv = y2p[t], zv = z2p[t], cv = c2p[t];
            #pragma unroll
            for (int q = 0; q < QPT; q++) {
                float lo, hi;
                ull a;
                a = fma2(xv.x, qx[q], fma2(yv.x, qy[q], fma2(zv.x, qz[q], cv.x)));
                unpk(a, lo, hi); accL[q] = fminf(accL[q], lo); accH[q] = fminf(accH[q], hi);
                a = fma2(xv.y, qx[q], fma2(yv.y, qy[q], fma2(zv.y, qz[q], cv.y)));
                unpk(a, lo, hi); accL[q] = fminf(accL[q], lo); accH[q] = fminf(accH[q], hi);
            }
        }
        #pragma unroll
        for (int q = 0; q < QPT; q++)
            atomicMin(&g_minxy[b*NPTS + q0 + q*BLK], fkey(fminf(accL[q], accH[q])));
    } else {
        float best[QPT];
        int bi[QPT];
        #pragma unroll
        for (int q = 0; q < QPT; q++) { best[q] = INFF; bi[q] = 0; }
        #pragma unroll 2
        for (int t = 0; t < CHUNK/4; t++) {
            const ulonglong2 xv = x2p[t], yv = y2p[t], zv = z2p[t], cv = c2p[t];
            const int cb = c0 + 4*t;
            #pragma unroll
            for (int q = 0; q < QPT; q++) {
                ull a0 = fma2(xv.x, qx[q], fma2(yv.x, qy[q], fma2(zv.x, qz[q], cv.x)));
                ull a1 = fma2(xv.y, qx[q], fma2(yv.y, qy[q], fma2(zv.y, qz[q], cv.y)));
                float v0, v1, v2, v3;
                unpk(a0, v0, v1); unpk(a1, v2, v3);
                const float mg = fminf(fminf(v0, v1), fminf(v2, v3));
                if (mg < best[q]) {   // rare (~9 hits per 8192 candidates)
                    if (v0 < best[q]) { best[q] = v0; bi[q] = cb;     }
                    if (v1 < best[q]) { best[q] = v1; bi[q] = cb + 1; }
                    if (v2 < best[q]) { best[q] = v2; bi[q] = cb + 2; }
                    if (v3 < best[q]) { best[q] = v3; bi[q] = cb + 3; }
                }
            }
        }
        #pragma unroll
        for (int q = 0; q < QPT; q++)
            atomicMin(&g_closest[b*NPTS + q0 + q*BLK],
                      ((ull)fkey(best[q]) << 32) | (unsigned)bi[q]);
    }
}

// Finalization: per-element losses, warp-shuffle reduce, last-block combine
// (deterministic fixed-order trees; ticket only selects WHO combines).
__global__ void __launch_bounds__(FBLK_T) final_kernel(const float* __restrict__ pred_sdfs,
                                                       const float* __restrict__ pred_cols,
                                                       const float* __restrict__ ref_sdfs,
                                                       const float* __restrict__ ref_cols,
                                                       float* __restrict__ out) {
    const int i = blockIdx.x * FBLK_T + threadIdx.x;   // [0, BB*NPTS)
    const int b = i >> 13;
    const int lane = threadIdx.x & 31;
    const int wid = threadIdx.x >> 5;

    const ull p = g_closest[i];
    const unsigned idx = (unsigned)(p & 0xFFFFFFFFu);
    const float d_yx = fmaxf(funkey((unsigned)(p >> 32)) + g_rc[i], 0.f);
    const float d_xy = fmaxf(funkey(g_minxy[i]) + g_pc[i], 0.f);

    const float* pc = pred_cols + (size_t)i * 3;
    const float* rc = ref_cols + ((size_t)(b << 13) + idx) * 3;
    double vals[4];
    vals[0] = fabsf(ref_sdfs[(b << 13) + idx] - pred_sdfs[i]);
    vals[1] = (double)(fabsf(rc[0]-pc[0]) + fabsf(rc[1]-pc[1]) + fabsf(rc[2]-pc[2]));
    vals[2] = d_yx;
    vals[3] = d_xy;

    __shared__ double sred[4][4];   // [warp][k]
    #pragma unroll
    for (int k = 0; k < 4; k++) {
        double v = vals[k];
        #pragma unroll
        for (int s = 16; s > 0; s >>= 1) v += __shfl_down_sync(0xFFFFFFFFu, v, s);
        if (lane == 0) sred[wid][k] = v;
    }
    __syncthreads();
    if (threadIdx.x == 0) {
        #pragma unroll
        for (int k = 0; k < 4; k++)
            g_part[blockIdx.x * 4 + k] = sred[0][k] + sred[1][k] + sred[2][k] + sred[3][k];
    }

    __threadfence();
    __shared__ unsigned ticket;
    if (threadIdx.x == 0) ticket = atomicAdd(&g_ctr, 1u);
    __syncthreads();
    if (ticket != FBLKS - 1) return;

    __threadfence();
    volatile double* vp = (volatile double*)g_part;
    double tv[4];
    #pragma unroll
    for (int k = 0; k < 4; k++) tv[k] = vp[threadIdx.x * 4 + k];  // thread t = block t's partial
    #pragma unroll
    for (int k = 0; k < 4; k++) {
        double v = tv[k];
        #pragma unroll
        for (int s = 16; s > 0; s >>= 1) v += __shfl_down_sync(0xFFFFFFFFu, v, s);
        if (lane == 0) sred[wid][k] = v;
    }
    __syncthreads();
    if (threadIdx.x == 0) {
        double t0 = sred[0][0] + sred[1][0] + sred[2][0] + sred[3][0];
        double t1 = sred[0][1] + sred[1][1] + sred[2][1] + sred[3][1];
        double t2 = sred[0][2] + sred[1][2] + sred[2][2] + sred[3][2];
        double t3 = sred[0][3] + sred[1][3] + sred[2][3] + sred[3][3];
        out[0] = (float)(t0 / (double)(BB * NPTS));
        out[1] = (float)(t1 / (double)(BB * NPTS * 3));
        out[2] = (float)(t3 / (double)(BB * NPTS) + t2 / (double)(BB * NPTS));
    }
}

extern "C" void kernel_launch(void* const* d_in, const int* in_sizes, int n_in,
                              void* d_out, int out_size) {
    const float* pred_pts  = (const float*)d_in[0];
    const float* pred_sdfs = (const float*)d_in[1];
    const float* pred_cols = (const float*)d_in[2];
    const float* ref_pts   = (const float*)d_in[3];
    const float* ref_sdfs  = (const float*)d_in[4];
    const float* ref_cols  = (const float*)d_in[5];
    float* out = (float*)d_out;

    prep_kernel<<<(BB*NPTS + 255) / 256, 256>>>(pred_pts, ref_pts);
    dist_kernel<<<dim3(GX, 2*NSPLIT, BB), BLK>>>(pred_pts, ref_pts);
    final_kernel<<<FBLKS, FBLK_T>>>(pred_sdfs, pred_cols, ref_sdfs, ref_cols, out);
}